// round 1
// baseline (speedup 1.0000x reference)
#include <cuda_runtime.h>
#include <cuda_bf16.h>
#include <math.h>

#define Bn 8
#define C  64
#define G  8
#define H  64
#define W  64
#define HW 4096

// ---------------- scratch (no cudaMalloc allowed) ----------------
__device__ float g_bufA[Bn * C * G * HW];   // 16.7M floats
__device__ float g_bufB[Bn * C * G * HW];
__device__ float g_avg[Bn * C * G];
__device__ float g_max[Bn * C * G];
__device__ float g_ca[Bn * G * C * G];      // [b][gout][c][hin]
__device__ float g_f[Bn * 16 * HW];         // [b][pair*8+h][HW]
__device__ float g_sp[Bn * G * HW];         // [b][g][HW]
__device__ float g_wt[G * G * C * C * 9];   // [g][hin][c][co][9]

// ---------------- p4m group table: PERM[g][h] = idx(inv(g)*h) ----------------
__constant__ int PERM_c[8][8] = {
    {0,1,2,3,4,5,6,7},
    {3,0,1,2,5,6,7,4},
    {2,3,0,1,6,7,4,5},
    {1,2,3,0,7,4,5,6},
    {4,5,6,7,0,1,2,3},
    {5,6,7,4,3,0,1,2},
    {6,7,4,5,2,3,0,1},
    {7,4,5,6,1,2,3,0},
};

// wg[i,j] = w[si,sj] for wg = rot90^b( flip_lastaxis^a(w) ), g = a*4+b
__device__ __forceinline__ void srcIdx(int g, int i, int j, int K, int& si, int& sj) {
    int a = g >> 2, b = g & 3;
    int p, q;
    switch (b) {
        case 0: p = i;         q = j;         break;
        case 1: p = j;         q = K - 1 - i; break;
        case 2: p = K - 1 - i; q = K - 1 - j; break;
        default: p = K - 1 - j; q = i;        break;
    }
    if (a) q = K - 1 - q;
    si = p; sj = q;
}

__device__ __forceinline__ float sigmoidf(float x) { return 1.0f / (1.0f + expf(-x)); }

// ---------------- 1. BN(eval) + ReLU + per-(b,c,h) avg/max over HW ----------------
__global__ void bn_relu_stats_kernel(const float* __restrict__ x, float* __restrict__ y,
                                     const float* __restrict__ gamma, const float* __restrict__ beta,
                                     const float* __restrict__ mean,  const float* __restrict__ var,
                                     float* __restrict__ avgOut, float* __restrict__ maxOut) {
    int row = blockIdx.x;                 // (b*C + c)*G + h
    int c = (row / G) % C;
    float inv  = gamma[c] / sqrtf(var[c] + 2e-5f);
    float bias = beta[c] - mean[c] * inv;
    const float* xp = x + (size_t)row * HW;
    float* yp = y + (size_t)row * HW;
    float s = 0.f, m = 0.f;               // ReLU output >= 0
    for (int i = threadIdx.x; i < HW; i += 256) {
        float v = fmaxf(fmaf(xp[i], inv, bias), 0.f);
        yp[i] = v;
        s += v;
        m = fmaxf(m, v);
    }
    __shared__ float ss[256], sm[256];
    ss[threadIdx.x] = s; sm[threadIdx.x] = m;
    __syncthreads();
    for (int o = 128; o > 0; o >>= 1) {
        if (threadIdx.x < o) {
            ss[threadIdx.x] += ss[threadIdx.x + o];
            sm[threadIdx.x] = fmaxf(sm[threadIdx.x], sm[threadIdx.x + o]);
        }
        __syncthreads();
    }
    if (threadIdx.x == 0) {
        avgOut[row] = ss[0] * (1.0f / HW);
        maxOut[row] = sm[0];
    }
}

// ---------------- 2. channel attention: ca[b][g][c][h] ----------------
// mlp(v,g)[j] = sum_m relu( sum_j v[c,PERM[g][h]] * w1[m,j] ) * w2[j,m];  ca = sigmoid(mlp(avg)+mlp(max))
__global__ void channel_att_kernel(const float* __restrict__ avg, const float* __restrict__ mx,
                                   const float* __restrict__ w1, const float* __restrict__ w2,
                                   float* __restrict__ ca) {
    int b = blockIdx.x >> 3, g = blockIdx.x & 7;
    int t = threadIdx.x;                  // 0..511 == c*8+h
    int c = t >> 3, h = t & 7;
    int hp = PERM_c[g][h];
    float va = avg[(b * C + c) * G + hp];
    float vm = mx[(b * C + c) * G + hp];
    float w1a = w1[t], w1b = w1[512 + t];
    __shared__ float4 red[512];
    red[t] = make_float4(va * w1a, va * w1b, vm * w1a, vm * w1b);
    __syncthreads();
    for (int o = 256; o > 0; o >>= 1) {
        if (t < o) {
            float4 a = red[t], bb = red[t + o];
            red[t] = make_float4(a.x + bb.x, a.y + bb.y, a.z + bb.z, a.w + bb.w);
        }
        __syncthreads();
    }
    float4 hs = red[0];
    float h0 = fmaxf(hs.x, 0.f) + fmaxf(hs.z, 0.f);   // relu(avg-path) + relu(max-path), hidden 0
    float h1 = fmaxf(hs.y, 0.f) + fmaxf(hs.w, 0.f);   // hidden 1
    float o = h0 * w2[t * 2] + h1 * w2[t * 2 + 1];
    ca[(size_t)(b * G + g) * C * G + t] = sigmoidf(o);
}

// ---------------- 3. spatial features: mean/max over channel dim ----------------
__global__ void feat_kernel(const float* __restrict__ y, float* __restrict__ f) {
    int i = blockIdx.x * 256 + threadIdx.x;  // over Bn*G*HW
    int p = i & (HW - 1);
    int h = (i >> 12) & 7;
    int b = i >> 15;
    const float* base = y + ((size_t)(b * C) * G + h) * HW + p;
    float s = 0.f, m = -1e30f;
    for (int c = 0; c < C; c++) {
        float v = base[(size_t)c * G * HW];
        s += v;
        m = fmaxf(m, v);
    }
    f[((size_t)(b * 16) + h) * HW + p] = s * (1.0f / C);
    f[((size_t)(b * 16) + 8 + h) * HW + p] = m;
}

// ---------------- 4. spatial attention 7x7 conv, per g ----------------
__global__ void spatial_att_kernel(const float* __restrict__ f, const float* __restrict__ saw,
                                   float* __restrict__ sp) {
    int tile = blockIdx.x, g = blockIdx.y, b = blockIdx.z;
    int ty0 = (tile >> 2) * 16, tx0 = (tile & 3) * 16;
    __shared__ float fs[16][22 * 22];
    __shared__ float ws[16 * 49];
    int t = threadIdx.x;
    for (int i = t; i < 16 * 484; i += 256) {
        int k = i / 484, r = i % 484, ly = r / 22, lx = r % 22;
        int gy = ty0 - 3 + ly, gx = tx0 - 3 + lx;
        float v = 0.f;
        if ((unsigned)gy < H && (unsigned)gx < W)
            v = f[((size_t)(b * 16) + k) * HW + gy * W + gx];
        fs[k][ly * 22 + lx] = v;
    }
    for (int i = t; i < 784; i += 256) {
        int k = i / 49, r = i % 49, dy = r / 7, dx = r % 7;
        int pair = k >> 3, hh = k & 7;
        int si, sj; srcIdx(g, dy, dx, 7, si, sj);
        ws[i] = saw[(pair * 8 + PERM_c[g][hh]) * 49 + si * 7 + sj];
    }
    __syncthreads();
    int ly = t >> 4, lx = t & 15;
    float acc = 0.f;
    for (int k = 0; k < 16; k++)
        for (int dy = 0; dy < 7; dy++)
#pragma unroll
            for (int dx = 0; dx < 7; dx++)
                acc = fmaf(fs[k][(ly + dy) * 22 + lx + dx], ws[k * 49 + dy * 7 + dx], acc);
    sp[(size_t)(b * G + g) * HW + (ty0 + ly) * W + tx0 + lx] = sigmoidf(acc);
}

// ---------------- 5. transform conv weights into [g][hin][c][co][9] ----------------
__global__ void xform_w_kernel(const float* __restrict__ w, float* __restrict__ wt) {
    int idx = blockIdx.x * 256 + threadIdx.x;
    if (idx >= G * G * C * C * 9) return;
    int k   = idx % 9;
    int co  = (idx / 9) & 63;
    int c   = (idx / 576) & 63;
    int hin = (idx / (576 * 64)) & 7;
    int g   = idx / (576 * 64 * 8);
    int ki = k / 3, kj = k % 3, si, sj;
    srcIdx(g, ki, kj, 3, si, sj);
    wt[idx] = w[((size_t)(co * 64 + c) * 8 + PERM_c[g][hin]) * 9 + si * 3 + sj];
}

// ---------------- 6. main group conv (direct, tiled), optional fused residual ----------------
// out[b,co,g,y,x] = sum_{c,hin,ki,kj} y[b,c,hin,y+ki-1,x+kj-1]*ca[b,g,c,hin]*sp[b,g,y+ki-1,x+kj-1]
//                   * wt[g,hin,c,co,ki*3+kj]   (+ residual)
__global__ void __launch_bounds__(256, 2) conv_main_kernel(
        const float* __restrict__ y, const float* __restrict__ wt,
        const float* __restrict__ ca, const float* __restrict__ sp,
        const float* __restrict__ residual, float* __restrict__ out) {
    int tile = blockIdx.x, g = blockIdx.y, b = blockIdx.z;
    int ty0 = (tile >> 2) * 16, tx0 = (tile & 3) * 16;
    __shared__ float in_sm[18][19];
    __shared__ float sp_sm[18][19];
    __shared__ float w_sm[64 * 9];
    int t = threadIdx.x;

    // preload spatial attention tile (with halo) once
    for (int i = t; i < 18 * 18; i += 256) {
        int ly = i / 18, lx = i % 18;
        int gy = ty0 - 1 + ly, gx = tx0 - 1 + lx;
        float v = 0.f;
        if ((unsigned)gy < H && (unsigned)gx < W)
            v = sp[(size_t)(b * G + g) * HW + gy * W + gx];
        sp_sm[ly][lx] = v;
    }

    float acc[8][8];
#pragma unroll
    for (int i = 0; i < 8; i++)
#pragma unroll
        for (int q = 0; q < 8; q++) acc[i][q] = 0.f;

    int lane = t & 31, warp = t >> 5;
    int srow = lane >> 1;          // 0..15
    int sxb  = (lane & 1) * 8;     // 0 or 8
    int cob  = warp * 8;           // cout base

    __syncthreads();

    const float* ca_bg = ca + (size_t)(b * G + g) * C * G;
    for (int hin = 0; hin < G; ++hin) {
        for (int c = 0; c < C; ++c) {
            float cav = ca_bg[c * G + hin];
            const float* ysrc = y + ((size_t)(b * C + c) * G + hin) * HW;
            for (int i = t; i < 18 * 18; i += 256) {
                int ly = i / 18, lx = i % 18;
                int gy = ty0 - 1 + ly, gx = tx0 - 1 + lx;
                float v = 0.f;
                if ((unsigned)gy < H && (unsigned)gx < W)
                    v = ysrc[gy * W + gx] * cav * sp_sm[ly][lx];
                in_sm[ly][lx] = v;
            }
            const float* wsrc = wt + (size_t)((g * G + hin) * C + c) * 576;
            for (int i = t; i < 576; i += 256) w_sm[i] = wsrc[i];
            __syncthreads();

#pragma unroll
            for (int ki = 0; ki < 3; ++ki) {
#pragma unroll
                for (int kj = 0; kj < 3; ++kj) {
                    int k = ki * 3 + kj;
                    float iv[8];
#pragma unroll
                    for (int q = 0; q < 8; ++q) iv[q] = in_sm[srow + ki][sxb + q + kj];
                    float wv[8];
#pragma unroll
                    for (int i = 0; i < 8; ++i) wv[i] = w_sm[(cob + i) * 9 + k];
#pragma unroll
                    for (int i = 0; i < 8; ++i)
#pragma unroll
                        for (int q = 0; q < 8; ++q) acc[i][q] = fmaf(wv[i], iv[q], acc[i][q]);
                }
            }
            __syncthreads();
        }
    }

    int gy = ty0 + srow;
#pragma unroll
    for (int i = 0; i < 8; ++i) {
        int co = cob + i;
        size_t base = (((size_t)b * C + co) * G + g) * HW + gy * W + tx0 + sxb;
#pragma unroll
        for (int q = 0; q < 8; ++q) {
            float r = residual ? residual[base + q] : 0.f;
            out[base + q] = acc[i][q] + r;
        }
    }
}

// ---------------- launch ----------------
extern "C" void kernel_launch(void* const* d_in, const int* in_sizes, int n_in,
                              void* d_out, int out_size) {
    const float* x         = (const float*)d_in[0];
    const float* bn1_gamma = (const float*)d_in[1];
    const float* bn1_beta  = (const float*)d_in[2];
    const float* bn1_mean  = (const float*)d_in[3];
    const float* bn1_var   = (const float*)d_in[4];
    const float* w1        = (const float*)d_in[5];
    const float* ca1_w1    = (const float*)d_in[6];
    const float* ca1_w2    = (const float*)d_in[7];
    const float* sa1_w     = (const float*)d_in[8];
    const float* bn2_gamma = (const float*)d_in[9];
    const float* bn2_beta  = (const float*)d_in[10];
    const float* bn2_mean  = (const float*)d_in[11];
    const float* bn2_var   = (const float*)d_in[12];
    const float* w2        = (const float*)d_in[13];
    const float* ca2_w1    = (const float*)d_in[14];
    const float* ca2_w2    = (const float*)d_in[15];
    const float* sa2_w     = (const float*)d_in[16];
    float* out = (float*)d_out;

    float *bufA, *bufB, *avg, *mx, *ca, *f, *sp, *wt;
    cudaGetSymbolAddress((void**)&bufA, g_bufA);
    cudaGetSymbolAddress((void**)&bufB, g_bufB);
    cudaGetSymbolAddress((void**)&avg,  g_avg);
    cudaGetSymbolAddress((void**)&mx,   g_max);
    cudaGetSymbolAddress((void**)&ca,   g_ca);
    cudaGetSymbolAddress((void**)&f,    g_f);
    cudaGetSymbolAddress((void**)&sp,   g_sp);
    cudaGetSymbolAddress((void**)&wt,   g_wt);

    dim3 tg(16, 8, 8);

    // ---- layer 1 ----
    xform_w_kernel<<<(G * G * C * C * 9 + 255) / 256, 256>>>(w1, wt);
    bn_relu_stats_kernel<<<Bn * C * G, 256>>>(x, bufA, bn1_gamma, bn1_beta, bn1_mean, bn1_var, avg, mx);
    channel_att_kernel<<<Bn * G, 512>>>(avg, mx, ca1_w1, ca1_w2, ca);
    feat_kernel<<<Bn * G * HW / 256, 256>>>(bufA, f);
    spatial_att_kernel<<<tg, 256>>>(f, sa1_w, sp);
    conv_main_kernel<<<tg, 256>>>(bufA, wt, ca, sp, nullptr, bufB);

    // ---- layer 2 ----
    xform_w_kernel<<<(G * G * C * C * 9 + 255) / 256, 256>>>(w2, wt);
    bn_relu_stats_kernel<<<Bn * C * G, 256>>>(bufB, bufA, bn2_gamma, bn2_beta, bn2_mean, bn2_var, avg, mx);
    channel_att_kernel<<<Bn * G, 512>>>(avg, mx, ca2_w1, ca2_w2, ca);
    feat_kernel<<<Bn * G * HW / 256, 256>>>(bufA, f);
    spatial_att_kernel<<<tg, 256>>>(f, sa2_w, sp);
    conv_main_kernel<<<tg, 256>>>(bufA, wt, ca, sp, x, out);
}

// round 2
// speedup vs baseline: 1.1153x; 1.1153x over previous
#include <cuda_runtime.h>
#include <cuda_bf16.h>
#include <math.h>

#define Bn 8
#define C  64
#define G  8
#define H  64
#define W  64
#define HW 4096

// ---------------- scratch (no cudaMalloc allowed) ----------------
__device__ float g_bufA[Bn * C * G * HW];   // 16.7M floats
__device__ float g_bufB[Bn * C * G * HW];
__device__ float g_avg[Bn * C * G];
__device__ float g_max[Bn * C * G];
__device__ float g_ca[Bn * G * C * G];      // [b][gout][c][hin]
__device__ float g_f[Bn * 16 * HW];         // [b][pair*8+h][HW]
__device__ float g_sp[Bn * G * HW];         // [b][g][HW]
__device__ float g_wt[G * G * C * C * 9];   // [g][hin][c][k][co]

// ---------------- p4m group table: PERM[g][h] = idx(inv(g)*h) ----------------
__constant__ int PERM_c[8][8] = {
    {0,1,2,3,4,5,6,7},
    {3,0,1,2,5,6,7,4},
    {2,3,0,1,6,7,4,5},
    {1,2,3,0,7,4,5,6},
    {4,5,6,7,0,1,2,3},
    {5,6,7,4,3,0,1,2},
    {6,7,4,5,2,3,0,1},
    {7,4,5,6,1,2,3,0},
};

// wg[i,j] = w[si,sj] for wg = rot90^b( flip_lastaxis^a(w) ), g = a*4+b
__device__ __forceinline__ void srcIdx(int g, int i, int j, int K, int& si, int& sj) {
    int a = g >> 2, b = g & 3;
    int p, q;
    switch (b) {
        case 0: p = i;         q = j;         break;
        case 1: p = j;         q = K - 1 - i; break;
        case 2: p = K - 1 - i; q = K - 1 - j; break;
        default: p = K - 1 - j; q = i;        break;
    }
    if (a) q = K - 1 - q;
    si = p; sj = q;
}

__device__ __forceinline__ float sigmoidf(float x) { return 1.0f / (1.0f + expf(-x)); }

// packed f32x2 helpers
__device__ __forceinline__ unsigned long long dup2(float v) {
    unsigned long long r;
    asm("mov.b64 %0, {%1, %1};" : "=l"(r) : "f"(v));
    return r;
}
#define FFMA2(d, a, b) asm("fma.rn.f32x2 %0, %1, %2, %0;" : "+l"(d) : "l"(a), "l"(b))
#define UNPACK2(lo, hi, in) asm("mov.b64 {%0, %1}, %2;" : "=f"(lo), "=f"(hi) : "l"(in))

// ---------------- 1. BN(eval) + ReLU + per-(b,c,h) avg/max over HW ----------------
__global__ void bn_relu_stats_kernel(const float* __restrict__ x, float* __restrict__ y,
                                     const float* __restrict__ gamma, const float* __restrict__ beta,
                                     const float* __restrict__ mean,  const float* __restrict__ var,
                                     float* __restrict__ avgOut, float* __restrict__ maxOut) {
    int row = blockIdx.x;                 // (b*C + c)*G + h
    int c = (row / G) % C;
    float inv  = gamma[c] / sqrtf(var[c] + 2e-5f);
    float bias = beta[c] - mean[c] * inv;
    const float* xp = x + (size_t)row * HW;
    float* yp = y + (size_t)row * HW;
    float s = 0.f, m = 0.f;               // ReLU output >= 0
    for (int i = threadIdx.x; i < HW; i += 256) {
        float v = fmaxf(fmaf(xp[i], inv, bias), 0.f);
        yp[i] = v;
        s += v;
        m = fmaxf(m, v);
    }
    __shared__ float ss[256], sm[256];
    ss[threadIdx.x] = s; sm[threadIdx.x] = m;
    __syncthreads();
    for (int o = 128; o > 0; o >>= 1) {
        if (threadIdx.x < o) {
            ss[threadIdx.x] += ss[threadIdx.x + o];
            sm[threadIdx.x] = fmaxf(sm[threadIdx.x], sm[threadIdx.x + o]);
        }
        __syncthreads();
    }
    if (threadIdx.x == 0) {
        avgOut[row] = ss[0] * (1.0f / HW);
        maxOut[row] = sm[0];
    }
}

// ---------------- 2. channel attention: ca[b][g][c][h] ----------------
__global__ void channel_att_kernel(const float* __restrict__ avg, const float* __restrict__ mx,
                                   const float* __restrict__ w1, const float* __restrict__ w2,
                                   float* __restrict__ ca) {
    int b = blockIdx.x >> 3, g = blockIdx.x & 7;
    int t = threadIdx.x;                  // 0..511 == c*8+h
    int c = t >> 3, h = t & 7;
    int hp = PERM_c[g][h];
    float va = avg[(b * C + c) * G + hp];
    float vm = mx[(b * C + c) * G + hp];
    float w1a = w1[t], w1b = w1[512 + t];
    __shared__ float4 red[512];
    red[t] = make_float4(va * w1a, va * w1b, vm * w1a, vm * w1b);
    __syncthreads();
    for (int o = 256; o > 0; o >>= 1) {
        if (t < o) {
            float4 a = red[t], bb = red[t + o];
            red[t] = make_float4(a.x + bb.x, a.y + bb.y, a.z + bb.z, a.w + bb.w);
        }
        __syncthreads();
    }
    float4 hs = red[0];
    float h0 = fmaxf(hs.x, 0.f) + fmaxf(hs.z, 0.f);
    float h1 = fmaxf(hs.y, 0.f) + fmaxf(hs.w, 0.f);
    float o = h0 * w2[t * 2] + h1 * w2[t * 2 + 1];
    ca[(size_t)(b * G + g) * C * G + t] = sigmoidf(o);
}

// ---------------- 3. spatial features: mean/max over channel dim ----------------
__global__ void feat_kernel(const float* __restrict__ y, float* __restrict__ f) {
    int i = blockIdx.x * 256 + threadIdx.x;  // over Bn*G*HW
    int p = i & (HW - 1);
    int h = (i >> 12) & 7;
    int b = i >> 15;
    const float* base = y + ((size_t)(b * C) * G + h) * HW + p;
    float s = 0.f, m = -1e30f;
    for (int c = 0; c < C; c++) {
        float v = base[(size_t)c * G * HW];
        s += v;
        m = fmaxf(m, v);
    }
    f[((size_t)(b * 16) + h) * HW + p] = s * (1.0f / C);
    f[((size_t)(b * 16) + 8 + h) * HW + p] = m;
}

// ---------------- 4. spatial attention 7x7 conv, per g ----------------
__global__ void spatial_att_kernel(const float* __restrict__ f, const float* __restrict__ saw,
                                   float* __restrict__ sp) {
    int tile = blockIdx.x, g = blockIdx.y, b = blockIdx.z;
    int ty0 = (tile >> 2) * 16, tx0 = (tile & 3) * 16;
    __shared__ float fs[16][22 * 22];
    __shared__ float ws[16 * 49];
    int t = threadIdx.x;
    for (int i = t; i < 16 * 484; i += 256) {
        int k = i / 484, r = i % 484, ly = r / 22, lx = r % 22;
        int gy = ty0 - 3 + ly, gx = tx0 - 3 + lx;
        float v = 0.f;
        if ((unsigned)gy < H && (unsigned)gx < W)
            v = f[((size_t)(b * 16) + k) * HW + gy * W + gx];
        fs[k][ly * 22 + lx] = v;
    }
    for (int i = t; i < 784; i += 256) {
        int k = i / 49, r = i % 49, dy = r / 7, dx = r % 7;
        int pair = k >> 3, hh = k & 7;
        int si, sj; srcIdx(g, dy, dx, 7, si, sj);
        ws[i] = saw[(pair * 8 + PERM_c[g][hh]) * 49 + si * 7 + sj];
    }
    __syncthreads();
    int ly = t >> 4, lx = t & 15;
    float acc = 0.f;
    for (int k = 0; k < 16; k++)
        for (int dy = 0; dy < 7; dy++)
#pragma unroll
            for (int dx = 0; dx < 7; dx++)
                acc = fmaf(fs[k][(ly + dy) * 22 + lx + dx], ws[k * 49 + dy * 7 + dx], acc);
    sp[(size_t)(b * G + g) * HW + (ty0 + ly) * W + tx0 + lx] = sigmoidf(acc);
}

// ---------------- 5. transform conv weights into [g][hin][c][k][co] ----------------
__global__ void xform_w_kernel(const float* __restrict__ w, float* __restrict__ wt) {
    int idx = blockIdx.x * 256 + threadIdx.x;
    if (idx >= G * G * C * C * 9) return;
    int co  = idx & 63;
    int k   = (idx / 64) % 9;
    int c   = (idx / 576) & 63;
    int hin = (idx / (576 * 64)) & 7;
    int g   = idx / (576 * 64 * 8);
    int ki = k / 3, kj = k % 3, si, sj;
    srcIdx(g, ki, kj, 3, si, sj);
    wt[idx] = w[((size_t)(co * 64 + c) * 8 + PERM_c[g][hin]) * 9 + si * 3 + sj];
}

// ---------------- 6. main group conv (direct, tiled, packed f32x2) ----------------
// out[b,co,g,y,x] = sum_{c,hin,ki,kj} y[b,c,hin,y+ki-1,x+kj-1]*ca[b,g,c,hin]*sp[b,g,y+ki-1,x+kj-1]
//                   * wt[g,hin,c,(ki*3+kj),co]   (+ residual)
__global__ void __launch_bounds__(256, 2) conv_main_kernel(
        const float* __restrict__ y, const float* __restrict__ wt,
        const float* __restrict__ ca, const float* __restrict__ sp,
        const float* __restrict__ residual, float* __restrict__ out) {
    int tile = blockIdx.x, g = blockIdx.y, b = blockIdx.z;
    int ty0 = (tile >> 2) * 16, tx0 = (tile & 3) * 16;
    __shared__ __align__(16) float in_sm[18][19];
    __shared__ float sp_sm[18][19];
    __shared__ __align__(16) float w_sm[9 * 64];   // [k][co]
    int t = threadIdx.x;

    // preload spatial attention tile (with halo) once
    for (int i = t; i < 18 * 18; i += 256) {
        int ly = i / 18, lx = i % 18;
        int gy = ty0 - 1 + ly, gx = tx0 - 1 + lx;
        float v = 0.f;
        if ((unsigned)gy < H && (unsigned)gx < W)
            v = sp[(size_t)(b * G + g) * HW + gy * W + gx];
        sp_sm[ly][lx] = v;
    }

    // acc2[ip][q]: lo = co=cob+2*ip, hi = co=cob+2*ip+1, output column q
    unsigned long long acc2[4][8];
#pragma unroll
    for (int ip = 0; ip < 4; ip++)
#pragma unroll
        for (int q = 0; q < 8; q++) acc2[ip][q] = 0ull;

    int lane = t & 31, warp = t >> 5;
    int srow = lane >> 1;          // 0..15
    int sxb  = (lane & 1) * 8;     // 0 or 8
    int cob  = warp * 8;           // cout base

    __syncthreads();

    const float* ca_bg = ca + (size_t)(b * G + g) * C * G;
    for (int hin = 0; hin < G; ++hin) {
        for (int c = 0; c < C; ++c) {
            float cav = ca_bg[c * G + hin];
            const float* ysrc = y + ((size_t)(b * C + c) * G + hin) * HW;
            for (int i = t; i < 18 * 18; i += 256) {
                int ly = i / 18, lx = i % 18;
                int gy = ty0 - 1 + ly, gx = tx0 - 1 + lx;
                float v = 0.f;
                if ((unsigned)gy < H && (unsigned)gx < W)
                    v = ysrc[gy * W + gx] * cav * sp_sm[ly][lx];
                in_sm[ly][lx] = v;
            }
            const float* wsrc = wt + (size_t)((g * G + hin) * C + c) * 576;
            for (int i = t; i < 576; i += 256) w_sm[i] = wsrc[i];
            __syncthreads();

#pragma unroll
            for (int ki = 0; ki < 3; ++ki) {
                // load 10 input values once per ki, duplicate-pack for f32x2
                unsigned long long iv2[10];
#pragma unroll
                for (int j = 0; j < 10; ++j) iv2[j] = dup2(in_sm[srow + ki][sxb + j]);
#pragma unroll
                for (int kj = 0; kj < 3; ++kj) {
                    int k = ki * 3 + kj;
                    const ulonglong2* wp = (const ulonglong2*)&w_sm[k * 64 + cob];
                    ulonglong2 wa = wp[0];     // pairs (co0,co1),(co2,co3)
                    ulonglong2 wb = wp[1];     // pairs (co4,co5),(co6,co7)
                    unsigned long long wv2[4] = {wa.x, wa.y, wb.x, wb.y};
#pragma unroll
                    for (int ip = 0; ip < 4; ++ip)
#pragma unroll
                        for (int q = 0; q < 8; ++q)
                            FFMA2(acc2[ip][q], wv2[ip], iv2[kj + q]);
                }
            }
            __syncthreads();
        }
    }

    int gy = ty0 + srow;
#pragma unroll
    for (int ip = 0; ip < 4; ++ip) {
        int co0 = cob + 2 * ip;
        size_t base0 = (((size_t)b * C + co0) * G + g) * HW + gy * W + tx0 + sxb;
        size_t base1 = base0 + (size_t)G * HW;   // co0+1
#pragma unroll
        for (int q = 0; q < 8; ++q) {
            float lo, hi;
            UNPACK2(lo, hi, acc2[ip][q]);
            float r0 = residual ? residual[base0 + q] : 0.f;
            float r1 = residual ? residual[base1 + q] : 0.f;
            out[base0 + q] = lo + r0;
            out[base1 + q] = hi + r1;
        }
    }
}

// ---------------- launch ----------------
extern "C" void kernel_launch(void* const* d_in, const int* in_sizes, int n_in,
                              void* d_out, int out_size) {
    const float* x         = (const float*)d_in[0];
    const float* bn1_gamma = (const float*)d_in[1];
    const float* bn1_beta  = (const float*)d_in[2];
    const float* bn1_mean  = (const float*)d_in[3];
    const float* bn1_var   = (const float*)d_in[4];
    const float* w1        = (const float*)d_in[5];
    const float* ca1_w1    = (const float*)d_in[6];
    const float* ca1_w2    = (const float*)d_in[7];
    const float* sa1_w     = (const float*)d_in[8];
    const float* bn2_gamma = (const float*)d_in[9];
    const float* bn2_beta  = (const float*)d_in[10];
    const float* bn2_mean  = (const float*)d_in[11];
    const float* bn2_var   = (const float*)d_in[12];
    const float* w2        = (const float*)d_in[13];
    const float* ca2_w1    = (const float*)d_in[14];
    const float* ca2_w2    = (const float*)d_in[15];
    const float* sa2_w     = (const float*)d_in[16];
    float* out = (float*)d_out;

    float *bufA, *bufB, *avg, *mx, *ca, *f, *sp, *wt;
    cudaGetSymbolAddress((void**)&bufA, g_bufA);
    cudaGetSymbolAddress((void**)&bufB, g_bufB);
    cudaGetSymbolAddress((void**)&avg,  g_avg);
    cudaGetSymbolAddress((void**)&mx,   g_max);
    cudaGetSymbolAddress((void**)&ca,   g_ca);
    cudaGetSymbolAddress((void**)&f,    g_f);
    cudaGetSymbolAddress((void**)&sp,   g_sp);
    cudaGetSymbolAddress((void**)&wt,   g_wt);

    dim3 tg(16, 8, 8);

    // ---- layer 1 ----
    xform_w_kernel<<<(G * G * C * C * 9 + 255) / 256, 256>>>(w1, wt);
    bn_relu_stats_kernel<<<Bn * C * G, 256>>>(x, bufA, bn1_gamma, bn1_beta, bn1_mean, bn1_var, avg, mx);
    channel_att_kernel<<<Bn * G, 512>>>(avg, mx, ca1_w1, ca1_w2, ca);
    feat_kernel<<<Bn * G * HW / 256, 256>>>(bufA, f);
    spatial_att_kernel<<<tg, 256>>>(f, sa1_w, sp);
    conv_main_kernel<<<tg, 256>>>(bufA, wt, ca, sp, nullptr, bufB);

    // ---- layer 2 ----
    xform_w_kernel<<<(G * G * C * C * 9 + 255) / 256, 256>>>(w2, wt);
    bn_relu_stats_kernel<<<Bn * C * G, 256>>>(bufB, bufA, bn2_gamma, bn2_beta, bn2_mean, bn2_var, avg, mx);
    channel_att_kernel<<<Bn * G, 512>>>(avg, mx, ca2_w1, ca2_w2, ca);
    feat_kernel<<<Bn * G * HW / 256, 256>>>(bufA, f);
    spatial_att_kernel<<<tg, 256>>>(f, sa2_w, sp);
    conv_main_kernel<<<tg, 256>>>(bufA, wt, ca, sp, x, out);
}

// round 4
// speedup vs baseline: 2.4551x; 2.2014x over previous
#include <cuda_runtime.h>
#include <cuda_bf16.h>
#include <math.h>
#include <stdint.h>

#define Bn 8
#define C  64
#define G  8
#define H  64
#define W  64
#define HW 4096

// ---------------- scratch (no cudaMalloc allowed) ----------------
__device__ float g_bufA[Bn * C * G * HW];
__device__ float g_bufB[Bn * C * G * HW];
__device__ float g_avg[Bn * C * G];
__device__ float g_max[Bn * C * G];
__device__ float g_ca[Bn * G * C * G];        // [b][gout][c][hin]
__device__ float g_f[Bn * 16 * HW];
__device__ float g_sp[Bn * G * HW];
// bf16 split weights: [g][hin][chunk4][part2(hi/lo)][k9][co64][ck16] halves
__device__ unsigned int g_wtu[G * G * C * C * 9];   // = 2.36M u32 = 4.7M halves

// ---------------- p4m group table ----------------
__constant__ int PERM_c[8][8] = {
    {0,1,2,3,4,5,6,7},
    {3,0,1,2,5,6,7,4},
    {2,3,0,1,6,7,4,5},
    {1,2,3,0,7,4,5,6},
    {4,5,6,7,0,1,2,3},
    {5,6,7,4,3,0,1,2},
    {6,7,4,5,2,3,0,1},
    {7,4,5,6,1,2,3,0},
};

__device__ __forceinline__ void srcIdx(int g, int i, int j, int K, int& si, int& sj) {
    int a = g >> 2, b = g & 3;
    int p, q;
    switch (b) {
        case 0: p = i;         q = j;         break;
        case 1: p = j;         q = K - 1 - i; break;
        case 2: p = K - 1 - i; q = K - 1 - j; break;
        default: p = K - 1 - j; q = i;        break;
    }
    if (a) q = K - 1 - q;
    si = p; sj = q;
}

__device__ __forceinline__ float sigmoidf(float x) { return 1.0f / (1.0f + expf(-x)); }

// ---------------- 1. BN + ReLU + stats ----------------
__global__ void bn_relu_stats_kernel(const float* __restrict__ x, float* __restrict__ y,
                                     const float* __restrict__ gamma, const float* __restrict__ beta,
                                     const float* __restrict__ mean,  const float* __restrict__ var,
                                     float* __restrict__ avgOut, float* __restrict__ maxOut) {
    int row = blockIdx.x;
    int c = (row / G) % C;
    float inv  = gamma[c] / sqrtf(var[c] + 2e-5f);
    float bias = beta[c] - mean[c] * inv;
    const float* xp = x + (size_t)row * HW;
    float* yp = y + (size_t)row * HW;
    float s = 0.f, m = 0.f;
    for (int i = threadIdx.x; i < HW; i += 256) {
        float v = fmaxf(fmaf(xp[i], inv, bias), 0.f);
        yp[i] = v;
        s += v;
        m = fmaxf(m, v);
    }
    __shared__ float ss[256], sm[256];
    ss[threadIdx.x] = s; sm[threadIdx.x] = m;
    __syncthreads();
    for (int o = 128; o > 0; o >>= 1) {
        if (threadIdx.x < o) {
            ss[threadIdx.x] += ss[threadIdx.x + o];
            sm[threadIdx.x] = fmaxf(sm[threadIdx.x], sm[threadIdx.x + o]);
        }
        __syncthreads();
    }
    if (threadIdx.x == 0) {
        avgOut[row] = ss[0] * (1.0f / HW);
        maxOut[row] = sm[0];
    }
}

// ---------------- 2. channel attention ----------------
__global__ void channel_att_kernel(const float* __restrict__ avg, const float* __restrict__ mx,
                                   const float* __restrict__ w1, const float* __restrict__ w2,
                                   float* __restrict__ ca) {
    int b = blockIdx.x >> 3, g = blockIdx.x & 7;
    int t = threadIdx.x;
    int c = t >> 3, h = t & 7;
    int hp = PERM_c[g][h];
    float va = avg[(b * C + c) * G + hp];
    float vm = mx[(b * C + c) * G + hp];
    float w1a = w1[t], w1b = w1[512 + t];
    __shared__ float4 red[512];
    red[t] = make_float4(va * w1a, va * w1b, vm * w1a, vm * w1b);
    __syncthreads();
    for (int o = 256; o > 0; o >>= 1) {
        if (t < o) {
            float4 a = red[t], bb = red[t + o];
            red[t] = make_float4(a.x + bb.x, a.y + bb.y, a.z + bb.z, a.w + bb.w);
        }
        __syncthreads();
    }
    float4 hs = red[0];
    float h0 = fmaxf(hs.x, 0.f) + fmaxf(hs.z, 0.f);
    float h1 = fmaxf(hs.y, 0.f) + fmaxf(hs.w, 0.f);
    float o = h0 * w2[t * 2] + h1 * w2[t * 2 + 1];
    ca[(size_t)(b * G + g) * C * G + t] = sigmoidf(o);
}

// ---------------- 3. spatial features ----------------
__global__ void feat_kernel(const float* __restrict__ y, float* __restrict__ f) {
    int i = blockIdx.x * 256 + threadIdx.x;
    int p = i & (HW - 1);
    int h = (i >> 12) & 7;
    int b = i >> 15;
    const float* base = y + ((size_t)(b * C) * G + h) * HW + p;
    float s = 0.f, m = -1e30f;
    for (int c = 0; c < C; c++) {
        float v = base[(size_t)c * G * HW];
        s += v;
        m = fmaxf(m, v);
    }
    f[((size_t)(b * 16) + h) * HW + p] = s * (1.0f / C);
    f[((size_t)(b * 16) + 8 + h) * HW + p] = m;
}

// ---------------- 4. spatial attention 7x7 ----------------
__global__ void spatial_att_kernel(const float* __restrict__ f, const float* __restrict__ saw,
                                   float* __restrict__ sp) {
    int tile = blockIdx.x, g = blockIdx.y, b = blockIdx.z;
    int ty0 = (tile >> 2) * 16, tx0 = (tile & 3) * 16;
    __shared__ float fs[16][22 * 22];
    __shared__ float ws[16 * 49];
    int t = threadIdx.x;
    for (int i = t; i < 16 * 484; i += 256) {
        int k = i / 484, r = i % 484, ly = r / 22, lx = r % 22;
        int gy = ty0 - 3 + ly, gx = tx0 - 3 + lx;
        float v = 0.f;
        if ((unsigned)gy < H && (unsigned)gx < W)
            v = f[((size_t)(b * 16) + k) * HW + gy * W + gx];
        fs[k][ly * 22 + lx] = v;
    }
    for (int i = t; i < 784; i += 256) {
        int k = i / 49, r = i % 49, dy = r / 7, dx = r % 7;
        int pair = k >> 3, hh = k & 7;
        int si, sj; srcIdx(g, dy, dx, 7, si, sj);
        ws[i] = saw[(pair * 8 + PERM_c[g][hh]) * 49 + si * 7 + sj];
    }
    __syncthreads();
    int ly = t >> 4, lx = t & 15;
    float acc = 0.f;
    for (int k = 0; k < 16; k++)
        for (int dy = 0; dy < 7; dy++)
#pragma unroll
            for (int dx = 0; dx < 7; dx++)
                acc = fmaf(fs[k][(ly + dy) * 22 + lx + dx], ws[k * 49 + dy * 7 + dx], acc);
    sp[(size_t)(b * G + g) * HW + (ty0 + ly) * W + tx0 + lx] = sigmoidf(acc);
}

// ---------------- 5. transform+split weights: [g][hin][chunk][part][k][co][ck] bf16 ----------------
__global__ void xform_w_kernel(const float* __restrict__ w, unsigned int* __restrict__ wtu) {
    int idx = blockIdx.x * 256 + threadIdx.x;
    if (idx >= G * G * C * C * 9) return;
    int co  = idx & 63;
    int k   = (idx / 64) % 9;
    int c   = (idx / 576) & 63;
    int hin = (idx / 36864) & 7;
    int g   = idx / 294912;
    int ki = k / 3, kj = k % 3, si, sj;
    srcIdx(g, ki, kj, 3, si, sj);
    float val = w[((size_t)(co * 64 + c) * 8 + PERM_c[g][hin]) * 9 + si * 3 + sj];
    __nv_bfloat16 hv = __float2bfloat16(val);
    __nv_bfloat16 lv = __float2bfloat16(val - __bfloat162float(hv));
    int chunk = c >> 4, ckL = c & 15;
    __nv_bfloat16* wt = (__nv_bfloat16*)wtu;
    size_t base = ((((size_t)(g * 8 + hin) * 4 + chunk) * 2) * 9 + k) * 1024 + co * 16 + ckL;
    wt[base] = hv;              // part 0 (hi)
    wt[base + 9216] = lv;       // part 1 (lo)
}

// ---------------- 6. group conv via mma.sync bf16 (3-term split) ----------------
// smem layout (bytes): sp[6][68] f32 @0 (1664); xhi[6][68][16] bf16 @1664; xlo @14720;
// whi[9][64][16] bf16 @27776; wlo @46208; total 64640
#define SM_SP   0
#define SM_XHI  1664
#define SM_XLO  14720
#define SM_WHI  27776
#define SM_TOTAL 64640

#define MMA_BF16(d, a0,a1,a2,a3, b0,b1) \
    asm("mma.sync.aligned.m16n8k16.row.col.f32.bf16.bf16.f32 " \
        "{%0,%1,%2,%3},{%4,%5,%6,%7},{%8,%9},{%0,%1,%2,%3};" \
        : "+f"(d[0]), "+f"(d[1]), "+f"(d[2]), "+f"(d[3]) \
        : "r"(a0), "r"(a1), "r"(a2), "r"(a3), "r"(b0), "r"(b1))

__global__ void __launch_bounds__(256, 2) conv_mma_kernel(
        const float* __restrict__ y, const unsigned int* __restrict__ wtu,
        const float* __restrict__ ca, const float* __restrict__ sp,
        const float* __restrict__ residual, float* __restrict__ out) {
    extern __shared__ char smb[];
    float* sp_sm = (float*)(smb + SM_SP);

    int rg = blockIdx.x, g = blockIdx.y, b = blockIdx.z;
    int y0 = rg * 4;
    int t = threadIdx.x;
    int lane = t & 31, warp = t >> 5;
    int wc = warp >> 1, wn = warp & 1;      // co block, n half
    int gid = lane >> 2, tg = lane & 3;

    // spatial-attention tile: rows y0-1..y0+4, cols -1..64 -> [6][68]
    for (int i = t; i < 6 * 68; i += 256) {
        int r = i / 68, cc = i % 68;
        int gy = y0 - 1 + r, gx = cc - 1;
        float v = 0.f;
        if ((unsigned)gy < H && cc < 66 && (unsigned)gx < W)
            v = sp[(size_t)(b * G + g) * HW + gy * W + gx];
        sp_sm[i] = v;
    }

    float acc[16][4];
#pragma unroll
    for (int nb = 0; nb < 16; nb++)
#pragma unroll
        for (int q = 0; q < 4; q++) acc[nb][q] = 0.f;

    const float* ca_bg = ca + (size_t)(b * G + g) * C * G;
    const unsigned int* wt_g = wtu + (size_t)g * 294912;   // per-g block in u32
    const float* ysrc_b = y + (size_t)b * C * G * HW;

#pragma unroll 1
    for (int hin = 0; hin < 8; ++hin) {
#pragma unroll 1
        for (int chunk = 0; chunk < 4; ++chunk) {
            __syncthreads();   // previous compute done before refill
            // weights: copy both parts (hi+lo): per (hin,chunk) block = 9216 u32 = 2304 uint4
            {
                const uint4* wsrc = (const uint4*)(wt_g + (size_t)(hin * 4 + chunk) * 9216);
                uint4* wdst = (uint4*)(smb + SM_WHI);
                for (int i = t; i < 2304; i += 256) wdst[i] = wsrc[i];
            }
            // modulated input tile, split to bf16 hi/lo, layout [row][col][ck]
            {
                __nv_bfloat16* xhi = (__nv_bfloat16*)(smb + SM_XHI);
                __nv_bfloat16* xlo = (__nv_bfloat16*)(smb + SM_XLO);
                for (int i = t; i < 6336; i += 256) {        // 16ck*6r*66col
                    int ck = i / 396;
                    int rem = i - ck * 396;
                    int r = rem / 66, col = rem - r * 66;
                    int c = chunk * 16 + ck;
                    int gy = y0 - 1 + r, gx = col - 1;
                    float v = 0.f;
                    if ((unsigned)gy < H && (unsigned)gx < W)
                        v = ysrc_b[(size_t)(c * G + hin) * HW + gy * W + gx]
                            * ca_bg[c * G + hin] * sp_sm[r * 68 + col];
                    __nv_bfloat16 hv = __float2bfloat16(v);
                    __nv_bfloat16 lv = __float2bfloat16(v - __bfloat162float(hv));
                    int o = (r * 68 + col) * 16 + ck;
                    xhi[o] = hv;
                    xlo[o] = lv;
                }
            }
            __syncthreads();

            const unsigned int* xh = (const unsigned int*)(smb + SM_XHI);
            const unsigned int* xl = (const unsigned int*)(smb + SM_XLO);
            const unsigned int* wh = (const unsigned int*)(smb + SM_WHI);
            const unsigned int* wl = wh + 4608;
#pragma unroll 1
            for (int k = 0; k < 9; ++k) {
                int ki = k / 3, kj = k - ki * 3;
                int rowA = (wc * 16 + gid) * 8 + k * 512;
                unsigned int ah0 = wh[rowA + tg],     ah1 = wh[rowA + 64 + tg];
                unsigned int ah2 = wh[rowA + tg + 4], ah3 = wh[rowA + 64 + tg + 4];
                unsigned int al0 = wl[rowA + tg],     al1 = wl[rowA + 64 + tg];
                unsigned int al2 = wl[rowA + tg + 4], al3 = wl[rowA + 64 + tg + 4];
                int baseW = (ki * 68 + gid + kj) * 8 + tg;
#pragma unroll
                for (int nb = 0; nb < 16; ++nb) {
                    int r2 = 2 * wn + (nb >> 3);
                    int colb = (nb & 7) * 8;
                    int wi = baseW + (r2 * 68 + colb) * 8;
                    unsigned int bh0 = xh[wi], bh1 = xh[wi + 4];
                    unsigned int bl0 = xl[wi], bl1 = xl[wi + 4];
                    MMA_BF16(acc[nb], ah0, ah1, ah2, ah3, bh0, bh1);
                    MMA_BF16(acc[nb], ah0, ah1, ah2, ah3, bl0, bl1);
                    MMA_BF16(acc[nb], al0, al1, al2, al3, bh0, bh1);
                }
            }
        }
    }

    // epilogue: acc[nb] -> C[gid][2tg..2tg+1], C[gid+8][...]; rows=co, cols=pos
    int co = wc * 16 + gid;
#pragma unroll
    for (int nb = 0; nb < 16; ++nb) {
        int r2 = 2 * wn + (nb >> 3), colb = (nb & 7) * 8;
        int gy = y0 + r2, gx = colb + 2 * tg;
        size_t o0 = ((size_t)(b * C + co) * G + g) * HW + gy * W + gx;
        size_t o1 = o0 + (size_t)8 * G * HW;    // co+8
        float2 v0 = make_float2(acc[nb][0], acc[nb][1]);
        float2 v1 = make_float2(acc[nb][2], acc[nb][3]);
        if (residual) {
            float2 r0 = *(const float2*)(residual + o0);
            float2 r1 = *(const float2*)(residual + o1);
            v0.x += r0.x; v0.y += r0.y;
            v1.x += r1.x; v1.y += r1.y;
        }
        *(float2*)(out + o0) = v0;
        *(float2*)(out + o1) = v1;
    }
}

// ---------------- launch ----------------
extern "C" void kernel_launch(void* const* d_in, const int* in_sizes, int n_in,
                              void* d_out, int out_size) {
    const float* x         = (const float*)d_in[0];
    const float* bn1_gamma = (const float*)d_in[1];
    const float* bn1_beta  = (const float*)d_in[2];
    const float* bn1_mean  = (const float*)d_in[3];
    const float* bn1_var   = (const float*)d_in[4];
    const float* w1        = (const float*)d_in[5];
    const float* ca1_w1    = (const float*)d_in[6];
    const float* ca1_w2    = (const float*)d_in[7];
    const float* sa1_w     = (const float*)d_in[8];
    const float* bn2_gamma = (const float*)d_in[9];
    const float* bn2_beta  = (const float*)d_in[10];
    const float* bn2_mean  = (const float*)d_in[11];
    const float* bn2_var   = (const float*)d_in[12];
    const float* w2        = (const float*)d_in[13];
    const float* ca2_w1    = (const float*)d_in[14];
    const float* ca2_w2    = (const float*)d_in[15];
    const float* sa2_w     = (const float*)d_in[16];
    float* out = (float*)d_out;

    float *bufA, *bufB, *avg, *mx, *ca, *f, *sp;
    unsigned int* wtu;
    cudaGetSymbolAddress((void**)&bufA, g_bufA);
    cudaGetSymbolAddress((void**)&bufB, g_bufB);
    cudaGetSymbolAddress((void**)&avg,  g_avg);
    cudaGetSymbolAddress((void**)&mx,   g_max);
    cudaGetSymbolAddress((void**)&ca,   g_ca);
    cudaGetSymbolAddress((void**)&f,    g_f);
    cudaGetSymbolAddress((void**)&sp,   g_sp);
    cudaGetSymbolAddress((void**)&wtu,  g_wtu);

    cudaFuncSetAttribute(conv_mma_kernel, cudaFuncAttributeMaxDynamicSharedMemorySize, SM_TOTAL);

    dim3 tg(16, 8, 8);

    // ---- layer 1 ----
    xform_w_kernel<<<(G * G * C * C * 9 + 255) / 256, 256>>>(w1, wtu);
    bn_relu_stats_kernel<<<Bn * C * G, 256>>>(x, bufA, bn1_gamma, bn1_beta, bn1_mean, bn1_var, avg, mx);
    channel_att_kernel<<<Bn * G, 512>>>(avg, mx, ca1_w1, ca1_w2, ca);
    feat_kernel<<<Bn * G * HW / 256, 256>>>(bufA, f);
    spatial_att_kernel<<<tg, 256>>>(f, sa1_w, sp);
    conv_mma_kernel<<<tg, 256, SM_TOTAL>>>(bufA, wtu, ca, sp, nullptr, bufB);

    // ---- layer 2 ----
    xform_w_kernel<<<(G * G * C * C * 9 + 255) / 256, 256>>>(w2, wtu);
    bn_relu_stats_kernel<<<Bn * C * G, 256>>>(bufB, bufA, bn2_gamma, bn2_beta, bn2_mean, bn2_var, avg, mx);
    channel_att_kernel<<<Bn * G, 512>>>(avg, mx, ca2_w1, ca2_w2, ca);
    feat_kernel<<<Bn * G * HW / 256, 256>>>(bufA, f);
    spatial_att_kernel<<<tg, 256>>>(f, sa2_w, sp);
    conv_mma_kernel<<<tg, 256, SM_TOTAL>>>(bufA, wtu, ca, sp, x, out);
}

// round 6
// speedup vs baseline: 2.8910x; 1.1775x over previous
#include <cuda_runtime.h>
#include <cuda_bf16.h>
#include <math.h>
#include <stdint.h>

#define Bn 8
#define C  64
#define G  8
#define H  64
#define W  64
#define HW 4096

// ---------------- scratch (no cudaMalloc allowed) ----------------
__device__ float g_bufA[Bn * C * G * HW];
__device__ float g_bufB[Bn * C * G * HW];
__device__ float g_avg[Bn * C * G];
__device__ float g_max[Bn * C * G];
__device__ float g_ca[Bn * G * C * G];        // [b][gout][c][hin]
__device__ float g_f[Bn * 16 * HW];
__device__ float g_sp[Bn * G * HW];
// padded bf16 split weights: [g][hin][chunk4][part2][k9][co64][row=12 u32 (16 halves + 8 pad)]
__device__ unsigned int g_wtu[3538944];

// ---------------- p4m group table ----------------
__constant__ int PERM_c[8][8] = {
    {0,1,2,3,4,5,6,7},
    {3,0,1,2,5,6,7,4},
    {2,3,0,1,6,7,4,5},
    {1,2,3,0,7,4,5,6},
    {4,5,6,7,0,1,2,3},
    {5,6,7,4,3,0,1,2},
    {6,7,4,5,2,3,0,1},
    {7,4,5,6,1,2,3,0},
};

__device__ __forceinline__ void srcIdx(int g, int i, int j, int K, int& si, int& sj) {
    int a = g >> 2, b = g & 3;
    int p, q;
    switch (b) {
        case 0: p = i;         q = j;         break;
        case 1: p = j;         q = K - 1 - i; break;
        case 2: p = K - 1 - i; q = K - 1 - j; break;
        default: p = K - 1 - j; q = i;        break;
    }
    if (a) q = K - 1 - q;
    si = p; sj = q;
}

__device__ __forceinline__ float sigmoidf(float x) { return 1.0f / (1.0f + expf(-x)); }

// ---------------- 1. BN + ReLU + stats ----------------
__global__ void bn_relu_stats_kernel(const float* __restrict__ x, float* __restrict__ y,
                                     const float* __restrict__ gamma, const float* __restrict__ beta,
                                     const float* __restrict__ mean,  const float* __restrict__ var,
                                     float* __restrict__ avgOut, float* __restrict__ maxOut) {
    int row = blockIdx.x;
    int c = (row / G) % C;
    float inv  = gamma[c] / sqrtf(var[c] + 2e-5f);
    float bias = beta[c] - mean[c] * inv;
    const float* xp = x + (size_t)row * HW;
    float* yp = y + (size_t)row * HW;
    float s = 0.f, m = 0.f;
    for (int i = threadIdx.x; i < HW; i += 256) {
        float v = fmaxf(fmaf(xp[i], inv, bias), 0.f);
        yp[i] = v;
        s += v;
        m = fmaxf(m, v);
    }
    __shared__ float ss[256], sm[256];
    ss[threadIdx.x] = s; sm[threadIdx.x] = m;
    __syncthreads();
    for (int o = 128; o > 0; o >>= 1) {
        if (threadIdx.x < o) {
            ss[threadIdx.x] += ss[threadIdx.x + o];
            sm[threadIdx.x] = fmaxf(sm[threadIdx.x], sm[threadIdx.x + o]);
        }
        __syncthreads();
    }
    if (threadIdx.x == 0) {
        avgOut[row] = ss[0] * (1.0f / HW);
        maxOut[row] = sm[0];
    }
}

// ---------------- 2. channel attention ----------------
__global__ void channel_att_kernel(const float* __restrict__ avg, const float* __restrict__ mx,
                                   const float* __restrict__ w1, const float* __restrict__ w2,
                                   float* __restrict__ ca) {
    int b = blockIdx.x >> 3, g = blockIdx.x & 7;
    int t = threadIdx.x;
    int c = t >> 3, h = t & 7;
    int hp = PERM_c[g][h];
    float va = avg[(b * C + c) * G + hp];
    float vm = mx[(b * C + c) * G + hp];
    float w1a = w1[t], w1b = w1[512 + t];
    __shared__ float4 red[512];
    red[t] = make_float4(va * w1a, va * w1b, vm * w1a, vm * w1b);
    __syncthreads();
    for (int o = 256; o > 0; o >>= 1) {
        if (t < o) {
            float4 a = red[t], bb = red[t + o];
            red[t] = make_float4(a.x + bb.x, a.y + bb.y, a.z + bb.z, a.w + bb.w);
        }
        __syncthreads();
    }
    float4 hs = red[0];
    float h0 = fmaxf(hs.x, 0.f) + fmaxf(hs.z, 0.f);
    float h1 = fmaxf(hs.y, 0.f) + fmaxf(hs.w, 0.f);
    float o = h0 * w2[t * 2] + h1 * w2[t * 2 + 1];
    ca[(size_t)(b * G + g) * C * G + t] = sigmoidf(o);
}

// ---------------- 3. spatial features ----------------
__global__ void feat_kernel(const float* __restrict__ y, float* __restrict__ f) {
    int i = blockIdx.x * 256 + threadIdx.x;
    int p = i & (HW - 1);
    int h = (i >> 12) & 7;
    int b = i >> 15;
    const float* base = y + ((size_t)(b * C) * G + h) * HW + p;
    float s = 0.f, m = -1e30f;
    for (int c = 0; c < C; c++) {
        float v = base[(size_t)c * G * HW];
        s += v;
        m = fmaxf(m, v);
    }
    f[((size_t)(b * 16) + h) * HW + p] = s * (1.0f / C);
    f[((size_t)(b * 16) + 8 + h) * HW + p] = m;
}

// ---------------- 4. spatial attention 7x7 ----------------
__global__ void spatial_att_kernel(const float* __restrict__ f, const float* __restrict__ saw,
                                   float* __restrict__ sp) {
    int tile = blockIdx.x, g = blockIdx.y, b = blockIdx.z;
    int ty0 = (tile >> 2) * 16, tx0 = (tile & 3) * 16;
    __shared__ float fs[16][22 * 22];
    __shared__ float ws[16 * 49];
    int t = threadIdx.x;
    for (int i = t; i < 16 * 484; i += 256) {
        int k = i / 484, r = i % 484, ly = r / 22, lx = r % 22;
        int gy = ty0 - 3 + ly, gx = tx0 - 3 + lx;
        float v = 0.f;
        if ((unsigned)gy < H && (unsigned)gx < W)
            v = f[((size_t)(b * 16) + k) * HW + gy * W + gx];
        fs[k][ly * 22 + lx] = v;
    }
    for (int i = t; i < 784; i += 256) {
        int k = i / 49, r = i % 49, dy = r / 7, dx = r % 7;
        int pair = k >> 3, hh = k & 7;
        int si, sj; srcIdx(g, dy, dx, 7, si, sj);
        ws[i] = saw[(pair * 8 + PERM_c[g][hh]) * 49 + si * 7 + sj];
    }
    __syncthreads();
    int ly = t >> 4, lx = t & 15;
    float acc = 0.f;
    for (int k = 0; k < 16; k++)
        for (int dy = 0; dy < 7; dy++)
#pragma unroll
            for (int dx = 0; dx < 7; dx++)
                acc = fmaf(fs[k][(ly + dy) * 22 + lx + dx], ws[k * 49 + dy * 7 + dx], acc);
    sp[(size_t)(b * G + g) * HW + (ty0 + ly) * W + tx0 + lx] = sigmoidf(acc);
}

// ---------------- 5. transform+split weights into padded layout ----------------
// [g][hin][chunk][part][k][co] rows of 12 u32 (16 halves data + 8 pad)
__global__ void xform_w_kernel(const float* __restrict__ w, unsigned int* __restrict__ wtu) {
    int idx = blockIdx.x * 256 + threadIdx.x;
    if (idx >= G * G * C * C * 9) return;
    int co  = idx & 63;
    int k   = (idx / 64) % 9;
    int c   = (idx / 576) & 63;
    int hin = (idx / 36864) & 7;
    int g   = idx / 294912;
    int ki = k / 3, kj = k % 3, si, sj;
    srcIdx(g, ki, kj, 3, si, sj);
    float val = w[((size_t)(co * 64 + c) * 8 + PERM_c[g][hin]) * 9 + si * 3 + sj];
    __nv_bfloat16 hv = __float2bfloat16(val);
    __nv_bfloat16 lv = __float2bfloat16(val - __bfloat162float(hv));
    int chunk = c >> 4, ck = c & 15;
    __nv_bfloat16* wt = (__nv_bfloat16*)wtu;
    // per-part block = 9*64 rows * 12 u32 = 6912 u32 = 13824 halves
    size_t blk = (size_t)(((g * 8 + hin) * 4 + chunk) * 2);
    size_t rowh = (size_t)(k * 64 + co) * 24;   // 24 halves per row
    wt[blk * 13824 + rowh + ck] = hv;                 // part 0 (hi)
    wt[(blk + 1) * 13824 + rowh + ck] = lv;           // part 1 (lo)
}

// ---------------- 6. group conv via mma.sync bf16 (3-term split) + ldmatrix ----------------
// smem bytes (48B padded rows, 16B aligned):
// sp[6][68] f32 @0 (1664); xhi @1664 (408 rows*48 = 19584); xlo @21248;
// whi @40832 (576 rows*48 = 27648); wlo @68480; total 96128
#define SMB_XHI 1664
#define SMB_XLO 21248
#define SMB_WHI 40832
#define SM_TOTAL 96128

#define MMA_BF16(d, a0,a1,a2,a3, b0,b1) \
    asm("mma.sync.aligned.m16n8k16.row.col.f32.bf16.bf16.f32 " \
        "{%0,%1,%2,%3},{%4,%5,%6,%7},{%8,%9},{%0,%1,%2,%3};" \
        : "+f"(d[0]), "+f"(d[1]), "+f"(d[2]), "+f"(d[3]) \
        : "r"(a0), "r"(a1), "r"(a2), "r"(a3), "r"(b0), "r"(b1))

#define LDSM4(r, addr) \
    asm volatile("ldmatrix.sync.aligned.m8n8.x4.shared.b16 {%0,%1,%2,%3}, [%4];" \
        : "=r"((r)[0]), "=r"((r)[1]), "=r"((r)[2]), "=r"((r)[3]) : "r"(addr))

__global__ void __launch_bounds__(256, 2) conv_mma_kernel(
        const float* __restrict__ y, const unsigned int* __restrict__ wtu,
        const float* __restrict__ ca, const float* __restrict__ sp,
        const float* __restrict__ residual, float* __restrict__ out) {
    extern __shared__ char smb[];
    float* sp_sm = (float*)smb;
    uint32_t sb = (uint32_t)__cvta_generic_to_shared(smb);
    const uint32_t sXhi = sb + SMB_XHI;
    const uint32_t sXlo = sb + SMB_XLO;
    const uint32_t sWhi = sb + SMB_WHI;

    int rg = blockIdx.x, g = blockIdx.y, b = blockIdx.z;
    int y0 = rg * 4;
    int t = threadIdx.x;
    int lane = t & 31, warp = t >> 5;
    int wc = warp >> 1, wn = warp & 1;      // co block, row half
    int gid = lane >> 2, tg = lane & 3;
    int li = lane & 7, lm = lane >> 3;

    // ldmatrix lane byte-offsets (48B row stride, 16B aligned)
    // A (m16k16 row-major): m0=rows0-7/k0-7, m1=rows8-15/k0-7, m2=rows0-7/k8-15, m3=rows8-15/k8-15
    uint32_t aLane = (uint32_t)((wc * 16 + (lm & 1) * 8 + li) * 48 + (lm >> 1) * 16);
    // B (n8k16, rows=n): m0=(n0-7,k0-7), m1=(n0-7,k8-15), m2=(n8-15,k0-7), m3=(n8-15,k8-15)
    uint32_t bLane = (uint32_t)((li + (lm >> 1) * 8) * 48 + (lm & 1) * 16);

    // spatial-attention tile: rows y0-1..y0+4, cols -1..64 -> [6][68]
    for (int i = t; i < 6 * 68; i += 256) {
        int r = i / 68, cc = i % 68;
        int gy = y0 - 1 + r, gx = cc - 1;
        float v = 0.f;
        if ((unsigned)gy < H && cc < 66 && (unsigned)gx < W)
            v = sp[(size_t)(b * G + g) * HW + gy * W + gx];
        sp_sm[i] = v;
    }

    float acc[16][4];
#pragma unroll
    for (int nb = 0; nb < 16; nb++)
#pragma unroll
        for (int q = 0; q < 4; q++) acc[nb][q] = 0.f;

    const float* ca_bg = ca + (size_t)(b * G + g) * C * G;
    const unsigned int* wt_g = wtu + (size_t)g * 442368;
    const float* ysrc_b = y + (size_t)b * C * G * HW;

#pragma unroll 1
    for (int hin = 0; hin < 8; ++hin) {
#pragma unroll 1
        for (int chunk = 0; chunk < 4; ++chunk) {
            __syncthreads();   // previous compute done before refill
            // weights: padded copy, both parts = 13824 u32 = 3456 uint4
            {
                const uint4* wsrc = (const uint4*)(wt_g + (size_t)(hin * 4 + chunk) * 13824);
                uint4* wdst = (uint4*)(smb + SMB_WHI);
                for (int i = t; i < 3456; i += 256) wdst[i] = wsrc[i];
            }
            // modulated input tile, split to bf16 hi/lo, padded rows of 24 halves
            {
                __nv_bfloat16* xhi = (__nv_bfloat16*)(smb + SMB_XHI);
                __nv_bfloat16* xlo = (__nv_bfloat16*)(smb + SMB_XLO);
                for (int i = t; i < 6336; i += 256) {        // 16ck*6r*66col
                    int ck = i / 396;
                    int rem = i - ck * 396;
                    int r = rem / 66, col = rem - r * 66;
                    int c = chunk * 16 + ck;
                    int gy = y0 - 1 + r, gx = col - 1;
                    float v = 0.f;
                    if ((unsigned)gy < H && (unsigned)gx < W)
                        v = ysrc_b[(size_t)(c * G + hin) * HW + gy * W + gx]
                            * ca_bg[c * G + hin] * sp_sm[r * 68 + col];
                    __nv_bfloat16 hv = __float2bfloat16(v);
                    __nv_bfloat16 lv = __float2bfloat16(v - __bfloat162float(hv));
                    int o = (r * 68 + col) * 24 + ck;
                    xhi[o] = hv;
                    xlo[o] = lv;
                }
            }
            __syncthreads();

#pragma unroll 1
            for (int ki = 0; ki < 3; ++ki) {
#pragma unroll
                for (int kj = 0; kj < 3; ++kj) {
                    int k = ki * 3 + kj;
                    uint32_t aa = sWhi + (uint32_t)k * 3072 + aLane;   // 64 rows * 48B per k
                    uint32_t ah[4], al[4];
                    LDSM4(ah, aa);
                    LDSM4(al, aa + 27648);
#pragma unroll
                    for (int rr = 0; rr < 2; ++rr) {
                        uint32_t boff = (uint32_t)(((2 * wn + rr + ki) * 68 + kj) * 48) + bLane;
#pragma unroll
                        for (int cpp = 0; cpp < 4; ++cpp) {
                            uint32_t off = boff + (uint32_t)(cpp * 16 * 48);
                            uint32_t bh[4], bl[4];
                            LDSM4(bh, sXhi + off);
                            LDSM4(bl, sXlo + off);
                            int nb = rr * 8 + cpp * 2;
                            MMA_BF16(acc[nb],     ah[0], ah[1], ah[2], ah[3], bh[0], bh[1]);
                            MMA_BF16(acc[nb],     ah[0], ah[1], ah[2], ah[3], bl[0], bl[1]);
                            MMA_BF16(acc[nb],     al[0], al[1], al[2], al[3], bh[0], bh[1]);
                            MMA_BF16(acc[nb + 1], ah[0], ah[1], ah[2], ah[3], bh[2], bh[3]);
                            MMA_BF16(acc[nb + 1], ah[0], ah[1], ah[2], ah[3], bl[2], bl[3]);
                            MMA_BF16(acc[nb + 1], al[0], al[1], al[2], al[3], bh[2], bh[3]);
                        }
                    }
                }
            }
        }
    }

    // epilogue: acc[nb] -> rows=co, cols=pos
    int co = wc * 16 + gid;
#pragma unroll
    for (int nb = 0; nb < 16; ++nb) {
        int r2 = 2 * wn + (nb >> 3), colb = (nb & 7) * 8;
        int gy = y0 + r2, gx = colb + 2 * tg;
        size_t o0 = ((size_t)(b * C + co) * G + g) * HW + gy * W + gx;
        size_t o1 = o0 + (size_t)8 * G * HW;    // co+8
        float2 v0 = make_float2(acc[nb][0], acc[nb][1]);
        float2 v1 = make_float2(acc[nb][2], acc[nb][3]);
        if (residual) {
            float2 r0 = *(const float2*)(residual + o0);
            float2 r1 = *(const float2*)(residual + o1);
            v0.x += r0.x; v0.y += r0.y;
            v1.x += r1.x; v1.y += r1.y;
        }
        *(float2*)(out + o0) = v0;
        *(float2*)(out + o1) = v1;
    }
}

// ---------------- launch ----------------
extern "C" void kernel_launch(void* const* d_in, const int* in_sizes, int n_in,
                              void* d_out, int out_size) {
    const float* x         = (const float*)d_in[0];
    const float* bn1_gamma = (const float*)d_in[1];
    const float* bn1_beta  = (const float*)d_in[2];
    const float* bn1_mean  = (const float*)d_in[3];
    const float* bn1_var   = (const float*)d_in[4];
    const float* w1        = (const float*)d_in[5];
    const float* ca1_w1    = (const float*)d_in[6];
    const float* ca1_w2    = (const float*)d_in[7];
    const float* sa1_w     = (const float*)d_in[8];
    const float* bn2_gamma = (const float*)d_in[9];
    const float* bn2_beta  = (const float*)d_in[10];
    const float* bn2_mean  = (const float*)d_in[11];
    const float* bn2_var   = (const float*)d_in[12];
    const float* w2        = (const float*)d_in[13];
    const float* ca2_w1    = (const float*)d_in[14];
    const float* ca2_w2    = (const float*)d_in[15];
    const float* sa2_w     = (const float*)d_in[16];
    float* out = (float*)d_out;

    float *bufA, *bufB, *avg, *mx, *ca, *f, *sp;
    unsigned int* wtu;
    cudaGetSymbolAddress((void**)&bufA, g_bufA);
    cudaGetSymbolAddress((void**)&bufB, g_bufB);
    cudaGetSymbolAddress((void**)&avg,  g_avg);
    cudaGetSymbolAddress((void**)&mx,   g_max);
    cudaGetSymbolAddress((void**)&ca,   g_ca);
    cudaGetSymbolAddress((void**)&f,    g_f);
    cudaGetSymbolAddress((void**)&sp,   g_sp);
    cudaGetSymbolAddress((void**)&wtu,  g_wtu);

    cudaFuncSetAttribute(conv_mma_kernel, cudaFuncAttributeMaxDynamicSharedMemorySize, SM_TOTAL);

    dim3 tg(16, 8, 8);

    // ---- layer 1 ----
    xform_w_kernel<<<(G * G * C * C * 9 + 255) / 256, 256>>>(w1, wtu);
    bn_relu_stats_kernel<<<Bn * C * G, 256>>>(x, bufA, bn1_gamma, bn1_beta, bn1_mean, bn1_var, avg, mx);
    channel_att_kernel<<<Bn * G, 512>>>(avg, mx, ca1_w1, ca1_w2, ca);
    feat_kernel<<<Bn * G * HW / 256, 256>>>(bufA, f);
    spatial_att_kernel<<<tg, 256>>>(f, sa1_w, sp);
    conv_mma_kernel<<<tg, 256, SM_TOTAL>>>(bufA, wtu, ca, sp, nullptr, bufB);

    // ---- layer 2 ----
    xform_w_kernel<<<(G * G * C * C * 9 + 255) / 256, 256>>>(w2, wtu);
    bn_relu_stats_kernel<<<Bn * C * G, 256>>>(bufB, bufA, bn2_gamma, bn2_beta, bn2_mean, bn2_var, avg, mx);
    channel_att_kernel<<<Bn * G, 512>>>(avg, mx, ca2_w1, ca2_w2, ca);
    feat_kernel<<<Bn * G * HW / 256, 256>>>(bufA, f);
    spatial_att_kernel<<<tg, 256>>>(f, sa2_w, sp);
    conv_mma_kernel<<<tg, 256, SM_TOTAL>>>(bufA, wtu, ca, sp, x, out);
}

// round 8
// speedup vs baseline: 4.7088x; 1.6288x over previous
#include <cuda_runtime.h>
#include <cuda_bf16.h>
#include <cuda_fp16.h>
#include <math.h>
#include <stdint.h>

#define Bn 8
#define C  64
#define G  8
#define H  64
#define W  64
#define HW 4096

// ---------------- scratch (no cudaMalloc allowed) ----------------
__device__ float g_bufA[Bn * C * G * HW];
__device__ float g_bufB[Bn * C * G * HW];
__device__ float g_avg[Bn * C * G];
__device__ float g_max[Bn * C * G];
__device__ float g_ca[Bn * G * C * G];        // [b][gout][c][hin]
__device__ float g_f[Bn * 16 * HW];
__device__ float g_sp[Bn * G * HW];
// padded fp16 weights: [g][hin][chunk4][k9][co64][row = 12 u32 (16 halves + 8 pad)]
__device__ unsigned int g_wtu[1769472];

// ---------------- p4m group table ----------------
__constant__ int PERM_c[8][8] = {
    {0,1,2,3,4,5,6,7},
    {3,0,1,2,5,6,7,4},
    {2,3,0,1,6,7,4,5},
    {1,2,3,0,7,4,5,6},
    {4,5,6,7,0,1,2,3},
    {5,6,7,4,3,0,1,2},
    {6,7,4,5,2,3,0,1},
    {7,4,5,6,1,2,3,0},
};

__device__ __forceinline__ void srcIdx(int g, int i, int j, int K, int& si, int& sj) {
    int a = g >> 2, b = g & 3;
    int p, q;
    switch (b) {
        case 0: p = i;         q = j;         break;
        case 1: p = j;         q = K - 1 - i; break;
        case 2: p = K - 1 - i; q = K - 1 - j; break;
        default: p = K - 1 - j; q = i;        break;
    }
    if (a) q = K - 1 - q;
    si = p; sj = q;
}

__device__ __forceinline__ float sigmoidf(float x) { return 1.0f / (1.0f + expf(-x)); }

// ---------------- 1. BN + ReLU + stats ----------------
__global__ void bn_relu_stats_kernel(const float* __restrict__ x, float* __restrict__ y,
                                     const float* __restrict__ gamma, const float* __restrict__ beta,
                                     const float* __restrict__ mean,  const float* __restrict__ var,
                                     float* __restrict__ avgOut, float* __restrict__ maxOut) {
    int row = blockIdx.x;
    int c = (row / G) % C;
    float inv  = gamma[c] / sqrtf(var[c] + 2e-5f);
    float bias = beta[c] - mean[c] * inv;
    const float* xp = x + (size_t)row * HW;
    float* yp = y + (size_t)row * HW;
    float s = 0.f, m = 0.f;
    for (int i = threadIdx.x; i < HW; i += 256) {
        float v = fmaxf(fmaf(xp[i], inv, bias), 0.f);
        yp[i] = v;
        s += v;
        m = fmaxf(m, v);
    }
    __shared__ float ss[256], sm[256];
    ss[threadIdx.x] = s; sm[threadIdx.x] = m;
    __syncthreads();
    for (int o = 128; o > 0; o >>= 1) {
        if (threadIdx.x < o) {
            ss[threadIdx.x] += ss[threadIdx.x + o];
            sm[threadIdx.x] = fmaxf(sm[threadIdx.x], sm[threadIdx.x + o]);
        }
        __syncthreads();
    }
    if (threadIdx.x == 0) {
        avgOut[row] = ss[0] * (1.0f / HW);
        maxOut[row] = sm[0];
    }
}

// ---------------- 2. channel attention ----------------
__global__ void channel_att_kernel(const float* __restrict__ avg, const float* __restrict__ mx,
                                   const float* __restrict__ w1, const float* __restrict__ w2,
                                   float* __restrict__ ca) {
    int b = blockIdx.x >> 3, g = blockIdx.x & 7;
    int t = threadIdx.x;
    int c = t >> 3, h = t & 7;
    int hp = PERM_c[g][h];
    float va = avg[(b * C + c) * G + hp];
    float vm = mx[(b * C + c) * G + hp];
    float w1a = w1[t], w1b = w1[512 + t];
    __shared__ float4 red[512];
    red[t] = make_float4(va * w1a, va * w1b, vm * w1a, vm * w1b);
    __syncthreads();
    for (int o = 256; o > 0; o >>= 1) {
        if (t < o) {
            float4 a = red[t], bb = red[t + o];
            red[t] = make_float4(a.x + bb.x, a.y + bb.y, a.z + bb.z, a.w + bb.w);
        }
        __syncthreads();
    }
    float4 hs = red[0];
    float h0 = fmaxf(hs.x, 0.f) + fmaxf(hs.z, 0.f);
    float h1 = fmaxf(hs.y, 0.f) + fmaxf(hs.w, 0.f);
    float o = h0 * w2[t * 2] + h1 * w2[t * 2 + 1];
    ca[(size_t)(b * G + g) * C * G + t] = sigmoidf(o);
}

// ---------------- 3. spatial features ----------------
__global__ void feat_kernel(const float* __restrict__ y, float* __restrict__ f) {
    int i = blockIdx.x * 256 + threadIdx.x;
    int p = i & (HW - 1);
    int h = (i >> 12) & 7;
    int b = i >> 15;
    const float* base = y + ((size_t)(b * C) * G + h) * HW + p;
    float s = 0.f, m = -1e30f;
    for (int c = 0; c < C; c++) {
        float v = base[(size_t)c * G * HW];
        s += v;
        m = fmaxf(m, v);
    }
    f[((size_t)(b * 16) + h) * HW + p] = s * (1.0f / C);
    f[((size_t)(b * 16) + 8 + h) * HW + p] = m;
}

// ---------------- 4. spatial attention 7x7 ----------------
__global__ void spatial_att_kernel(const float* __restrict__ f, const float* __restrict__ saw,
                                   float* __restrict__ sp) {
    int tile = blockIdx.x, g = blockIdx.y, b = blockIdx.z;
    int ty0 = (tile >> 2) * 16, tx0 = (tile & 3) * 16;
    __shared__ float fs[16][22 * 22];
    __shared__ float ws[16 * 49];
    int t = threadIdx.x;
    for (int i = t; i < 16 * 484; i += 256) {
        int k = i / 484, r = i % 484, ly = r / 22, lx = r % 22;
        int gy = ty0 - 3 + ly, gx = tx0 - 3 + lx;
        float v = 0.f;
        if ((unsigned)gy < H && (unsigned)gx < W)
            v = f[((size_t)(b * 16) + k) * HW + gy * W + gx];
        fs[k][ly * 22 + lx] = v;
    }
    for (int i = t; i < 784; i += 256) {
        int k = i / 49, r = i % 49, dy = r / 7, dx = r % 7;
        int pair = k >> 3, hh = k & 7;
        int si, sj; srcIdx(g, dy, dx, 7, si, sj);
        ws[i] = saw[(pair * 8 + PERM_c[g][hh]) * 49 + si * 7 + sj];
    }
    __syncthreads();
    int ly = t >> 4, lx = t & 15;
    float acc = 0.f;
    for (int k = 0; k < 16; k++)
        for (int dy = 0; dy < 7; dy++)
#pragma unroll
            for (int dx = 0; dx < 7; dx++)
                acc = fmaf(fs[k][(ly + dy) * 22 + lx + dx], ws[k * 49 + dy * 7 + dx], acc);
    sp[(size_t)(b * G + g) * HW + (ty0 + ly) * W + tx0 + lx] = sigmoidf(acc);
}

// ---------------- 5. transform weights into padded fp16 layout ----------------
// [g][hin][chunk][k][co] rows of 12 u32 (16 halves data + 8 pad)
__global__ void xform_w_kernel(const float* __restrict__ w, unsigned int* __restrict__ wtu) {
    int idx = blockIdx.x * 256 + threadIdx.x;
    if (idx >= G * G * C * C * 9) return;
    int co  = idx & 63;
    int k   = (idx / 64) % 9;
    int c   = (idx / 576) & 63;
    int hin = (idx / 36864) & 7;
    int g   = idx / 294912;
    int ki = k / 3, kj = k % 3, si, sj;
    srcIdx(g, ki, kj, 3, si, sj);
    float val = w[((size_t)(co * 64 + c) * 8 + PERM_c[g][hin]) * 9 + si * 3 + sj];
    int chunk = c >> 4, ck = c & 15;
    __half* wt = (__half*)wtu;
    // per (hin,chunk) block = 9*64 rows * 24 halves = 13824 halves
    size_t blk = (size_t)((g * 8 + hin) * 4 + chunk);
    size_t rowh = (size_t)(k * 64 + co) * 24;
    wt[blk * 13824 + rowh + ck] = __float2half(val);
}

// ---------------- 6. group conv via mma.sync fp16 + ldmatrix ----------------
// smem bytes (48B padded rows, 16B aligned):
// sp[6][68] f32 @0 (1664); X @1664 (408 rows*48 = 19584); W @21248 (576 rows*48 = 27648)
#define SMB_X 1664
#define SMB_W 21248
#define SM_TOTAL 48896

#define MMA_F16(d, a0,a1,a2,a3, b0,b1) \
    asm("mma.sync.aligned.m16n8k16.row.col.f32.f16.f16.f32 " \
        "{%0,%1,%2,%3},{%4,%5,%6,%7},{%8,%9},{%0,%1,%2,%3};" \
        : "+f"(d[0]), "+f"(d[1]), "+f"(d[2]), "+f"(d[3]) \
        : "r"(a0), "r"(a1), "r"(a2), "r"(a3), "r"(b0), "r"(b1))

#define LDSM4(r, addr) \
    asm volatile("ldmatrix.sync.aligned.m8n8.x4.shared.b16 {%0,%1,%2,%3}, [%4];" \
        : "=r"((r)[0]), "=r"((r)[1]), "=r"((r)[2]), "=r"((r)[3]) : "r"(addr))

__global__ void __launch_bounds__(256, 2) conv_mma_kernel(
        const float* __restrict__ y, const unsigned int* __restrict__ wtu,
        const float* __restrict__ ca, const float* __restrict__ sp,
        const float* __restrict__ residual, float* __restrict__ out) {
    extern __shared__ char smb[];
    float* sp_sm = (float*)smb;
    uint32_t sb = (uint32_t)__cvta_generic_to_shared(smb);
    const uint32_t sX = sb + SMB_X;
    const uint32_t sW = sb + SMB_W;

    int rg = blockIdx.x, g = blockIdx.y, b = blockIdx.z;
    int y0 = rg * 4;
    int t = threadIdx.x;
    int lane = t & 31, warp = t >> 5;
    int wc = warp >> 1, wn = warp & 1;      // co block, row half
    int gid = lane >> 2, tg = lane & 3;
    int li = lane & 7, lm = lane >> 3;

    // ldmatrix lane byte-offsets (48B row stride, 16B aligned)
    uint32_t aLane = (uint32_t)((wc * 16 + (lm & 1) * 8 + li) * 48 + (lm >> 1) * 16);
    uint32_t bLane = (uint32_t)((li + (lm >> 1) * 8) * 48 + (lm & 1) * 16);

    // spatial-attention tile: rows y0-1..y0+4, cols -1..64 -> [6][68]
    for (int i = t; i < 6 * 68; i += 256) {
        int r = i / 68, cc = i % 68;
        int gy = y0 - 1 + r, gx = cc - 1;
        float v = 0.f;
        if ((unsigned)gy < H && cc < 66 && (unsigned)gx < W)
            v = sp[(size_t)(b * G + g) * HW + gy * W + gx];
        sp_sm[i] = v;
    }

    float acc[16][4];
#pragma unroll
    for (int nb = 0; nb < 16; nb++)
#pragma unroll
        for (int q = 0; q < 4; q++) acc[nb][q] = 0.f;

    const float* ca_bg = ca + (size_t)(b * G + g) * C * G;
    const unsigned int* wt_g = wtu + (size_t)g * 221184;
    const float* ysrc_b = y + (size_t)b * C * G * HW;

#pragma unroll 1
    for (int hin = 0; hin < 8; ++hin) {
#pragma unroll 1
        for (int chunk = 0; chunk < 4; ++chunk) {
            __syncthreads();   // previous compute done before refill
            // weights: padded copy = 6912 u32 = 1728 uint4
            {
                const uint4* wsrc = (const uint4*)(wt_g + (size_t)(hin * 4 + chunk) * 6912);
                uint4* wdst = (uint4*)(smb + SMB_W);
                for (int i = t; i < 1728; i += 256) wdst[i] = wsrc[i];
            }
            // modulated input tile, fp16, padded rows of 24 halves
            {
                __half* xs = (__half*)(smb + SMB_X);
                for (int i = t; i < 6336; i += 256) {        // 16ck*6r*66col
                    int ck = i / 396;
                    int rem = i - ck * 396;
                    int r = rem / 66, col = rem - r * 66;
                    int c = chunk * 16 + ck;
                    int gy = y0 - 1 + r, gx = col - 1;
                    float v = 0.f;
                    if ((unsigned)gy < H && (unsigned)gx < W)
                        v = ysrc_b[(size_t)(c * G + hin) * HW + gy * W + gx]
                            * ca_bg[c * G + hin] * sp_sm[r * 68 + col];
                    xs[(r * 68 + col) * 24 + ck] = __float2half(v);
                }
            }
            __syncthreads();

#pragma unroll 1
            for (int ki = 0; ki < 3; ++ki) {
#pragma unroll
                for (int kj = 0; kj < 3; ++kj) {
                    int k = ki * 3 + kj;
                    uint32_t aa = sW + (uint32_t)k * 3072 + aLane;   // 64 rows * 48B per k
                    uint32_t ah[4];
                    LDSM4(ah, aa);
#pragma unroll
                    for (int rr = 0; rr < 2; ++rr) {
                        uint32_t boff = (uint32_t)(((2 * wn + rr + ki) * 68 + kj) * 48) + bLane;
#pragma unroll
                        for (int cpp = 0; cpp < 4; ++cpp) {
                            uint32_t off = boff + (uint32_t)(cpp * 16 * 48);
                            uint32_t bh[4];
                            LDSM4(bh, sX + off);
                            int nb = rr * 8 + cpp * 2;
                            MMA_F16(acc[nb],     ah[0], ah[1], ah[2], ah[3], bh[0], bh[1]);
                            MMA_F16(acc[nb + 1], ah[0], ah[1], ah[2], ah[3], bh[2], bh[3]);
                        }
                    }
                }
            }
        }
    }

    // epilogue: acc[nb] -> rows=co, cols=pos
    int co = wc * 16 + gid;
#pragma unroll
    for (int nb = 0; nb < 16; ++nb) {
        int r2 = 2 * wn + (nb >> 3), colb = (nb & 7) * 8;
        int gy = y0 + r2, gx = colb + 2 * tg;
        size_t o0 = ((size_t)(b * C + co) * G + g) * HW + gy * W + gx;
        size_t o1 = o0 + (size_t)8 * G * HW;    // co+8
        float2 v0 = make_float2(acc[nb][0], acc[nb][1]);
        float2 v1 = make_float2(acc[nb][2], acc[nb][3]);
        if (residual) {
            float2 r0 = *(const float2*)(residual + o0);
            float2 r1 = *(const float2*)(residual + o1);
            v0.x += r0.x; v0.y += r0.y;
            v1.x += r1.x; v1.y += r1.y;
        }
        *(float2*)(out + o0) = v0;
        *(float2*)(out + o1) = v1;
    }
}

// ---------------- launch ----------------
extern "C" void kernel_launch(void* const* d_in, const int* in_sizes, int n_in,
                              void* d_out, int out_size) {
    const float* x         = (const float*)d_in[0];
    const float* bn1_gamma = (const float*)d_in[1];
    const float* bn1_beta  = (const float*)d_in[2];
    const float* bn1_mean  = (const float*)d_in[3];
    const float* bn1_var   = (const float*)d_in[4];
    const float* w1        = (const float*)d_in[5];
    const float* ca1_w1    = (const float*)d_in[6];
    const float* ca1_w2    = (const float*)d_in[7];
    const float* sa1_w     = (const float*)d_in[8];
    const float* bn2_gamma = (const float*)d_in[9];
    const float* bn2_beta  = (const float*)d_in[10];
    const float* bn2_mean  = (const float*)d_in[11];
    const float* bn2_var   = (const float*)d_in[12];
    const float* w2        = (const float*)d_in[13];
    const float* ca2_w1    = (const float*)d_in[14];
    const float* ca2_w2    = (const float*)d_in[15];
    const float* sa2_w     = (const float*)d_in[16];
    float* out = (float*)d_out;

    float *bufA, *bufB, *avg, *mx, *ca, *f, *sp;
    unsigned int* wtu;
    cudaGetSymbolAddress((void**)&bufA, g_bufA);
    cudaGetSymbolAddress((void**)&bufB, g_bufB);
    cudaGetSymbolAddress((void**)&avg,  g_avg);
    cudaGetSymbolAddress((void**)&mx,   g_max);
    cudaGetSymbolAddress((void**)&ca,   g_ca);
    cudaGetSymbolAddress((void**)&f,    g_f);
    cudaGetSymbolAddress((void**)&sp,   g_sp);
    cudaGetSymbolAddress((void**)&wtu,  g_wtu);

    cudaFuncSetAttribute(conv_mma_kernel, cudaFuncAttributeMaxDynamicSharedMemorySize, SM_TOTAL);

    dim3 tg(16, 8, 8);

    // ---- layer 1 ----
    xform_w_kernel<<<(G * G * C * C * 9 + 255) / 256, 256>>>(w1, wtu);
    bn_relu_stats_kernel<<<Bn * C * G, 256>>>(x, bufA, bn1_gamma, bn1_beta, bn1_mean, bn1_var, avg, mx);
    channel_att_kernel<<<Bn * G, 512>>>(avg, mx, ca1_w1, ca1_w2, ca);
    feat_kernel<<<Bn * G * HW / 256, 256>>>(bufA, f);
    spatial_att_kernel<<<tg, 256>>>(f, sa1_w, sp);
    conv_mma_kernel<<<tg, 256, SM_TOTAL>>>(bufA, wtu, ca, sp, nullptr, bufB);

    // ---- layer 2 ----
    xform_w_kernel<<<(G * G * C * C * 9 + 255) / 256, 256>>>(w2, wtu);
    bn_relu_stats_kernel<<<Bn * C * G, 256>>>(bufB, bufA, bn2_gamma, bn2_beta, bn2_mean, bn2_var, avg, mx);
    channel_att_kernel<<<Bn * G, 512>>>(avg, mx, ca2_w1, ca2_w2, ca);
    feat_kernel<<<Bn * G * HW / 256, 256>>>(bufA, f);
    spatial_att_kernel<<<tg, 256>>>(f, sa2_w, sp);
    conv_mma_kernel<<<tg, 256, SM_TOTAL>>>(bufA, wtu, ca, sp, x, out);
}